// round 1
// baseline (speedup 1.0000x reference)
#include <cuda_runtime.h>
#include <cuda_bf16.h>

// Problem constants
#define B   32
#define CIN 128
#define HW  3136      // 56*56
#define HH  56
#define WW  56
#define COUT 256
#define E_  4
#define R_  16
#define KDIM 1152     // CIN*9
#define KERN_PER_B (COUT*KDIM)   // 294912

__device__ float g_routing[B * E_];
__device__ float g_kern[(size_t)B * KERN_PER_B];   // 37.7 MB mixed weights

// ---------------------------------------------------------------------------
// Kernel 1: GAP + router MLP + softmax(logits/30)
// one block per sample, 256 threads (8 warps)
// ---------------------------------------------------------------------------
__global__ __launch_bounds__(256)
void router_kernel(const float* __restrict__ x,
                   const float* __restrict__ w1, const float* __restrict__ b1,
                   const float* __restrict__ w2, const float* __restrict__ b2)
{
    int b = blockIdx.x;
    int tid = threadIdx.x;
    int warp = tid >> 5;
    int lane = tid & 31;

    __shared__ float gap_s[CIN];
    __shared__ float h_s[R_];

    // GAP: warp per channel
    for (int c = warp; c < CIN; c += 8) {
        const float* p = x + ((size_t)b * CIN + c) * HW;
        float s = 0.f;
        for (int i = lane; i < HW; i += 32) s += p[i];
        #pragma unroll
        for (int off = 16; off > 0; off >>= 1)
            s += __shfl_down_sync(0xffffffffu, s, off);
        if (lane == 0) gap_s[c] = s * (1.0f / (float)HW);
    }
    __syncthreads();

    // h = relu(gap @ w1^T + b1), 16 threads
    if (tid < R_) {
        float s = b1[tid];
        const float* wr = w1 + tid * CIN;
        for (int c = 0; c < CIN; c++) s += gap_s[c] * wr[c];
        h_s[tid] = s > 0.f ? s : 0.f;
    }
    __syncthreads();

    // logits + softmax/temp, 1 thread
    if (tid == 0) {
        float lg[E_];
        float mx = -1e30f;
        #pragma unroll
        for (int e = 0; e < E_; e++) {
            float s = b2[e];
            const float* wr = w2 + e * R_;
            #pragma unroll
            for (int r = 0; r < R_; r++) s += h_s[r] * wr[r];
            lg[e] = s * (1.0f / 30.0f);
            mx = fmaxf(mx, lg[e]);
        }
        float denom = 0.f;
        #pragma unroll
        for (int e = 0; e < E_; e++) { lg[e] = expf(lg[e] - mx); denom += lg[e]; }
        float inv = 1.0f / denom;
        #pragma unroll
        for (int e = 0; e < E_; e++) g_routing[b * E_ + e] = lg[e] * inv;
    }
}

// ---------------------------------------------------------------------------
// Kernel 2: mix expert weights -> g_kern[b] = sum_e r[b,e] * convs[e]
// float4-vectorized; KERN_PER_B % 4 == 0
// ---------------------------------------------------------------------------
#define MIX_V4 ((size_t)B * KERN_PER_B / 4)
#define KPB4   (KERN_PER_B / 4)   // 73728

__global__ __launch_bounds__(256)
void mix_kernel(const float* __restrict__ convs)
{
    size_t idx = (size_t)blockIdx.x * blockDim.x + threadIdx.x;
    if (idx >= MIX_V4) return;
    int b  = (int)(idx / KPB4);
    int j4 = (int)(idx % KPB4);

    float r0 = g_routing[b * E_ + 0];
    float r1 = g_routing[b * E_ + 1];
    float r2 = g_routing[b * E_ + 2];
    float r3 = g_routing[b * E_ + 3];

    const float4* c4 = (const float4*)convs;
    float4 v0 = c4[0 * KPB4 + j4];
    float4 v1 = c4[1 * KPB4 + j4];
    float4 v2 = c4[2 * KPB4 + j4];
    float4 v3 = c4[3 * KPB4 + j4];

    float4 o;
    o.x = r0 * v0.x + r1 * v1.x + r2 * v2.x + r3 * v3.x;
    o.y = r0 * v0.y + r1 * v1.y + r2 * v2.y + r3 * v3.y;
    o.z = r0 * v0.z + r1 * v1.z + r2 * v2.z + r3 * v3.z;
    o.w = r0 * v0.w + r1 * v1.w + r2 * v2.w + r3 * v3.w;
    ((float4*)g_kern)[idx] = o;
}

// ---------------------------------------------------------------------------
// Kernel 3: per-sample implicit-GEMM conv
//   out[b] (COUT x HW) = kern[b] (COUT x KDIM) @ im2col(x[b]) (KDIM x HW)
// Classic 128x128x8 SGEMM tiling, 8x8 micro-tile, 256 threads.
// ---------------------------------------------------------------------------
#define BM 128
#define BN 128
#define BK 8
#define TM 8
#define TN 8

__global__ __launch_bounds__(256)
void conv_gemm_kernel(const float* __restrict__ x, float* __restrict__ out)
{
    const int b  = blockIdx.z;
    const int m0 = blockIdx.y * BM;
    const int n0 = blockIdx.x * BN;

    const float* A = g_kern + (size_t)b * KERN_PER_B;       // [COUT][KDIM]
    const float* X = x + (size_t)b * CIN * HW;              // [CIN][56][56]

    __shared__ float As[BK][BM];
    __shared__ float Bs[BK][BN];

    const int tid = threadIdx.x;
    const int tx = tid & 15;     // 0..15 -> n micro
    const int ty = tid >> 4;     // 0..15 -> m micro

    // A-load mapping: thread loads float4 at (row = tid/2, col = (tid&1)*4)
    const int a_row = tid >> 1;
    const int a_col = (tid & 1) * 4;

    // B-load mapping: thread covers n = tid&127, k rows (tid>>7)*4 .. +3
    const int b_n  = tid & 127;
    const int b_k0 = (tid >> 7) * 4;
    const int n_g  = n0 + b_n;
    const int oh   = n_g / WW;
    const int ow   = n_g - oh * WW;
    const bool n_ok = (n_g < HW);

    float acc[TM][TN];
    #pragma unroll
    for (int i = 0; i < TM; i++)
        #pragma unroll
        for (int j = 0; j < TN; j++) acc[i][j] = 0.f;

    float ra[TM], rb[TN];

    for (int kt = 0; kt < KDIM; kt += BK) {
        // --- load A tile (transposed into As[k][m]) ---
        float4 av = *(const float4*)(A + (size_t)(m0 + a_row) * KDIM + kt + a_col);
        As[a_col + 0][a_row] = av.x;
        As[a_col + 1][a_row] = av.y;
        As[a_col + 2][a_row] = av.z;
        As[a_col + 3][a_row] = av.w;

        // --- load B tile via on-the-fly im2col ---
        #pragma unroll
        for (int i = 0; i < 4; i++) {
            int k   = kt + b_k0 + i;
            int cin = k / 9;
            int rem = k - cin * 9;
            int kh  = rem / 3;
            int kw  = rem - kh * 3;
            int ih  = oh + kh - 1;
            int iw  = ow + kw - 1;
            float v = 0.f;
            if (n_ok && (unsigned)ih < (unsigned)HH && (unsigned)iw < (unsigned)WW)
                v = X[((size_t)cin * HH + ih) * WW + iw];
            Bs[b_k0 + i][b_n] = v;
        }
        __syncthreads();

        // --- compute ---
        #pragma unroll
        for (int kk = 0; kk < BK; kk++) {
            #pragma unroll
            for (int i = 0; i < TM; i++) ra[i] = As[kk][ty * TM + i];
            #pragma unroll
            for (int j = 0; j < TN; j++) rb[j] = Bs[kk][tx * TN + j];
            #pragma unroll
            for (int i = 0; i < TM; i++)
                #pragma unroll
                for (int j = 0; j < TN; j++)
                    acc[i][j] += ra[i] * rb[j];
        }
        __syncthreads();
    }

    // --- epilogue ---
    #pragma unroll
    for (int i = 0; i < TM; i++) {
        int m = m0 + ty * TM + i;
        float* orow = out + ((size_t)b * COUT + m) * HW;
        #pragma unroll
        for (int j = 0; j < TN; j++) {
            int n = n0 + tx * TN + j;
            if (n < HW) orow[n] = acc[i][j];
        }
    }
}

// ---------------------------------------------------------------------------
extern "C" void kernel_launch(void* const* d_in, const int* in_sizes, int n_in,
                              void* d_out, int out_size)
{
    const float* x     = (const float*)d_in[0];   // [32,128,56,56]
    const float* convs = (const float*)d_in[1];   // [4,256,128,3,3]
    const float* w1    = (const float*)d_in[2];   // [16,128]
    const float* b1    = (const float*)d_in[3];   // [16]
    const float* w2    = (const float*)d_in[4];   // [4,16]
    const float* b2    = (const float*)d_in[5];   // [4]
    float* out = (float*)d_out;                   // [32,256,56,56]

    router_kernel<<<B, 256>>>(x, w1, b1, w2, b2);

    int mix_blocks = (int)((MIX_V4 + 255) / 256);
    mix_kernel<<<mix_blocks, 256>>>(convs);

    dim3 grid((HW + BN - 1) / BN, COUT / BM, B);  // (25, 2, 32)
    conv_gemm_kernel<<<grid, 256>>>(x, out);
}

// round 3
// speedup vs baseline: 2.6221x; 2.6221x over previous
#include <cuda_runtime.h>
#include <cstdint>

// Problem constants
#define B   32
#define CIN 128
#define HW  3136      // 56*56
#define HH  56
#define WW  56
#define COUT 256
#define E_  4
#define R_  16
#define KDIM 1152     // CIN*9
#define KERN_PER_B (COUT*KDIM)   // 294912

__device__ float g_routing[B * E_];
__device__ float g_gap[B * CIN];
__device__ float g_kern[(size_t)B * KERN_PER_B];   // 37.7 MB mixed weights

// ---------------------------------------------------------------------------
// Kernel 1a: GAP — one block per (channel, sample), full-chip parallel
// ---------------------------------------------------------------------------
__global__ __launch_bounds__(128)
void gap_kernel(const float* __restrict__ x)
{
    int c = blockIdx.x;
    int b = blockIdx.y;
    const float4* p = (const float4*)(x + ((size_t)b * CIN + c) * HW);
    float s = 0.f;
    for (int i = threadIdx.x; i < HW / 4; i += 128) {
        float4 v = p[i];
        s += (v.x + v.y) + (v.z + v.w);
    }
    #pragma unroll
    for (int off = 16; off > 0; off >>= 1)
        s += __shfl_down_sync(0xffffffffu, s, off);
    __shared__ float ws[4];
    int warp = threadIdx.x >> 5, lane = threadIdx.x & 31;
    if (lane == 0) ws[warp] = s;
    __syncthreads();
    if (threadIdx.x == 0)
        g_gap[b * CIN + c] = (ws[0] + ws[1] + ws[2] + ws[3]) * (1.0f / (float)HW);
}

// ---------------------------------------------------------------------------
// Kernel 1b: router MLP + softmax(logits/30) — one small block per sample
// ---------------------------------------------------------------------------
__global__ __launch_bounds__(32)
void router_mlp_kernel(const float* __restrict__ w1, const float* __restrict__ b1,
                       const float* __restrict__ w2, const float* __restrict__ b2)
{
    int b = blockIdx.x;
    int tid = threadIdx.x;
    __shared__ float h_s[R_];
    if (tid < R_) {
        float s = b1[tid];
        const float* wr = w1 + tid * CIN;
        const float* gp = g_gap + b * CIN;
        for (int c = 0; c < CIN; c++) s += gp[c] * wr[c];
        h_s[tid] = s > 0.f ? s : 0.f;
    }
    __syncthreads();
    if (tid == 0) {
        float lg[E_];
        float mx = -1e30f;
        #pragma unroll
        for (int e = 0; e < E_; e++) {
            float s = b2[e];
            const float* wr = w2 + e * R_;
            #pragma unroll
            for (int r = 0; r < R_; r++) s += h_s[r] * wr[r];
            lg[e] = s * (1.0f / 30.0f);
            mx = fmaxf(mx, lg[e]);
        }
        float denom = 0.f;
        #pragma unroll
        for (int e = 0; e < E_; e++) { lg[e] = expf(lg[e] - mx); denom += lg[e]; }
        float inv = 1.0f / denom;
        #pragma unroll
        for (int e = 0; e < E_; e++) g_routing[b * E_ + e] = lg[e] * inv;
    }
}

// ---------------------------------------------------------------------------
// Kernel 2: mix expert weights -> g_kern[b] = sum_e r[b,e] * convs[e]
// ---------------------------------------------------------------------------
#define MIX_V4 ((size_t)B * KERN_PER_B / 4)
#define KPB4   (KERN_PER_B / 4)   // 73728

__global__ __launch_bounds__(256)
void mix_kernel(const float* __restrict__ convs)
{
    size_t idx = (size_t)blockIdx.x * blockDim.x + threadIdx.x;
    if (idx >= MIX_V4) return;
    int b  = (int)(idx / KPB4);
    int j4 = (int)(idx % KPB4);

    float r0 = g_routing[b * E_ + 0];
    float r1 = g_routing[b * E_ + 1];
    float r2 = g_routing[b * E_ + 2];
    float r3 = g_routing[b * E_ + 3];

    const float4* c4 = (const float4*)convs;
    float4 v0 = c4[0 * KPB4 + j4];
    float4 v1 = c4[1 * KPB4 + j4];
    float4 v2 = c4[2 * KPB4 + j4];
    float4 v3 = c4[3 * KPB4 + j4];

    float4 o;
    o.x = r0 * v0.x + r1 * v1.x + r2 * v2.x + r3 * v3.x;
    o.y = r0 * v0.y + r1 * v1.y + r2 * v2.y + r3 * v3.y;
    o.z = r0 * v0.z + r1 * v1.z + r2 * v2.z + r3 * v3.z;
    o.w = r0 * v0.w + r1 * v1.w + r2 * v2.w + r3 * v3.w;
    ((float4*)g_kern)[idx] = o;
}

// ---------------------------------------------------------------------------
// Kernel 3: per-sample implicit-GEMM conv using tf32 mma.sync tensor cores
//   out[b] (COUT x HW) = kern[b] (COUT x KDIM) @ im2col(x[b]) (KDIM x HW)
// Block tile 128x128x16, 8 warps (2x4), warp tile 64x32, mma m16n8k8.tf32.
// Ping-pong smem with register staging.
// ---------------------------------------------------------------------------
#define BM 128
#define BN 128
#define BK 16
#define SPAD 132   // 128 + 4 padding -> conflict-free fragment loads

__device__ __forceinline__ uint32_t cvt_tf32(float f) {
    uint32_t u;
    asm("cvt.rna.tf32.f32 %0, %1;" : "=r"(u) : "f"(f));
    return u;
}

__device__ __forceinline__ void mma_tf32(float* d, const uint32_t* a, const uint32_t* b) {
    asm volatile(
        "mma.sync.aligned.m16n8k8.row.col.f32.tf32.tf32.f32 "
        "{%0,%1,%2,%3}, {%4,%5,%6,%7}, {%8,%9}, {%0,%1,%2,%3};"
        : "+f"(d[0]), "+f"(d[1]), "+f"(d[2]), "+f"(d[3])
        : "r"(a[0]), "r"(a[1]), "r"(a[2]), "r"(a[3]),
          "r"(b[0]), "r"(b[1]));
}

__global__ __launch_bounds__(256, 2)
void conv_mma_kernel(const float* __restrict__ x, float* __restrict__ out)
{
    const int b  = blockIdx.z;
    const int m0 = blockIdx.y * BM;
    const int n0 = blockIdx.x * BN;

    const float* A = g_kern + (size_t)b * KERN_PER_B;   // [COUT][KDIM]
    const float* X = x + (size_t)b * CIN * HW;          // [CIN][56][56]

    __shared__ uint32_t As[2][BK][SPAD];
    __shared__ uint32_t Bs[2][BK][SPAD];

    const int tid  = threadIdx.x;
    const int warp = tid >> 5;
    const int lane = tid & 31;
    const int g    = lane >> 2;   // 0..7
    const int tig  = lane & 3;    // 0..3
    const int wm   = warp >> 2;   // 0..1  (m)
    const int wn   = warp & 3;    // 0..3  (n)

    // A staging: 2 float4 per thread. f4 idx = tid + i*256 -> row=(idx>>2), col4=(idx&3)
    const int a_row = tid >> 2;          // 0..63 (i adds 64)
    const int a_c4  = (tid & 3) * 4;     // k-col base

    // B staging (im2col): thread covers n = tid&127, 8 k-values at k0 = (tid>>7)*8
    const int b_n  = tid & 127;
    const int b_k0 = (tid >> 7) * 8;
    const int n_g  = n0 + b_n;
    const int oh   = n_g / WW;
    const int ow   = n_g - oh * WW;
    const bool n_ok = (n_g < HW);

    float4 aval[2];
    float  bval[8];

    float acc[4][4][4];
    #pragma unroll
    for (int mi = 0; mi < 4; mi++)
        #pragma unroll
        for (int ni = 0; ni < 4; ni++)
            #pragma unroll
            for (int r = 0; r < 4; r++) acc[mi][ni][r] = 0.f;

    // ---- global load into registers for tile at kt ----
    auto load_global = [&](int kt) {
        #pragma unroll
        for (int i = 0; i < 2; i++) {
            int row = a_row + i * 64;
            aval[i] = *(const float4*)(A + (size_t)(m0 + row) * KDIM + kt + a_c4);
        }
        #pragma unroll
        for (int i = 0; i < 8; i++) {
            int k   = kt + b_k0 + i;
            int cin = k / 9;
            int rem = k - cin * 9;
            int kh  = rem / 3;
            int kw  = rem - kh * 3;
            int ih  = oh + kh - 1;
            int iw  = ow + kw - 1;
            float v = 0.f;
            if (n_ok && (unsigned)ih < (unsigned)HH && (unsigned)iw < (unsigned)WW)
                v = X[((size_t)cin * HH + ih) * WW + iw];
            bval[i] = v;
        }
    };
    // ---- registers -> smem buffer (with tf32 rounding) ----
    auto store_smem = [&](int buf) {
        #pragma unroll
        for (int i = 0; i < 2; i++) {
            int row = a_row + i * 64;
            As[buf][a_c4 + 0][row] = cvt_tf32(aval[i].x);
            As[buf][a_c4 + 1][row] = cvt_tf32(aval[i].y);
            As[buf][a_c4 + 2][row] = cvt_tf32(aval[i].z);
            As[buf][a_c4 + 3][row] = cvt_tf32(aval[i].w);
        }
        #pragma unroll
        for (int i = 0; i < 8; i++)
            Bs[buf][b_k0 + i][b_n] = cvt_tf32(bval[i]);
    };

    load_global(0);
    store_smem(0);
    __syncthreads();

    const int NITER = KDIM / BK;   // 72
    for (int it = 0; it < NITER; it++) {
        const int buf = it & 1;
        const bool more = (it + 1) < NITER;
        if (more) load_global((it + 1) * BK);

        #pragma unroll
        for (int kk = 0; kk < 2; kk++) {
            const int k8 = kk * 8;
            uint32_t af[4][4], bf[4][2];
            #pragma unroll
            for (int mi = 0; mi < 4; mi++) {
                int m = wm * 64 + mi * 16 + g;
                af[mi][0] = As[buf][k8 + tig    ][m];
                af[mi][1] = As[buf][k8 + tig    ][m + 8];
                af[mi][2] = As[buf][k8 + tig + 4][m];
                af[mi][3] = As[buf][k8 + tig + 4][m + 8];
            }
            #pragma unroll
            for (int ni = 0; ni < 4; ni++) {
                int n = wn * 32 + ni * 8 + g;
                bf[ni][0] = Bs[buf][k8 + tig    ][n];
                bf[ni][1] = Bs[buf][k8 + tig + 4][n];
            }
            #pragma unroll
            for (int mi = 0; mi < 4; mi++)
                #pragma unroll
                for (int ni = 0; ni < 4; ni++)
                    mma_tf32(acc[mi][ni], af[mi], bf[ni]);
        }

        if (more) store_smem(buf ^ 1);
        __syncthreads();
    }

    // ---- epilogue: c layout m16n8 -> rows g, g+8; cols tig*2, tig*2+1 ----
    #pragma unroll
    for (int mi = 0; mi < 4; mi++) {
        int r0 = m0 + wm * 64 + mi * 16 + g;
        int r1 = r0 + 8;
        float* o0 = out + ((size_t)b * COUT + r0) * HW;
        float* o1 = out + ((size_t)b * COUT + r1) * HW;
        #pragma unroll
        for (int ni = 0; ni < 4; ni++) {
            int n = n0 + wn * 32 + ni * 8 + tig * 2;
            if (n < HW) {   // HW even, pairs aligned -> single predicate covers both
                *(float2*)(o0 + n) = make_float2(acc[mi][ni][0], acc[mi][ni][1]);
                *(float2*)(o1 + n) = make_float2(acc[mi][ni][2], acc[mi][ni][3]);
            }
        }
    }
}

// ---------------------------------------------------------------------------
extern "C" void kernel_launch(void* const* d_in, const int* in_sizes, int n_in,
                              void* d_out, int out_size)
{
    const float* x     = (const float*)d_in[0];   // [32,128,56,56]
    const float* convs = (const float*)d_in[1];   // [4,256,128,3,3]
    const float* w1    = (const float*)d_in[2];   // [16,128]
    const float* b1    = (const float*)d_in[3];   // [16]
    const float* w2    = (const float*)d_in[4];   // [4,16]
    const float* b2    = (const float*)d_in[5];   // [4]
    float* out = (float*)d_out;                   // [32,256,56,56]

    dim3 gap_grid(CIN, B);
    gap_kernel<<<gap_grid, 128>>>(x);
    router_mlp_kernel<<<B, 32>>>(w1, b1, w2, b2);

    int mix_blocks = (int)((MIX_V4 + 255) / 256);
    mix_kernel<<<mix_blocks, 256>>>(convs);

    dim3 grid((HW + BN - 1) / BN, COUT / BM, B);  // (25, 2, 32)
    conv_mma_kernel<<<grid, 256>>>(x, out);
}